// round 2
// baseline (speedup 1.0000x reference)
#include <cuda_runtime.h>
#include <stdint.h>

#define NN   20000
#define RR   32
#define EMBD 16
#define HID  128
#define NE   600000
#define NSEG (NN*RR)

#define EPB1 1024
#define EPB2 512
#define GRID1 672
#define GRID2 1280

// ---------------- device scratch (no runtime allocation allowed) ----------------
__device__ int      g_is64;
__device__ unsigned g_cnt_seg[NSEG];     // per-(dst,rel) edge counts
__device__ int      g_rel_cnt[RR];
__device__ int      g_rel_ptr[RR + 1];
__device__ int      g_rel_cur[RR];
__device__ int      g_srcA[NE];
__device__ int      g_dstA[NE];
__device__ int      g_relA[NE];
__device__ unsigned g_epack[NE];         // rel-sorted: src | dst<<16
__device__ float    g_einv[NE];          // rel-sorted: 1/count(dst,rel)
__device__ float    g_h1[NN * HID];      // hidden activations

__device__ __forceinline__ void red_add_v4(float* p, float a, float b, float c, float d) {
    asm volatile("red.global.add.v4.f32 [%0], {%1,%2,%3,%4};"
                 :: "l"(p), "f"(a), "f"(b), "f"(c), "f"(d) : "memory");
}

// ---------------- dtype sniff: int64 vs int32 edge indices ----------------
__global__ void k_sniff(const int* ei) {
    __shared__ int ok;
    if (threadIdx.x == 0) ok = 1;
    __syncthreads();
    // If data is int64 little-endian, words at odd positions are high words == 0.
    // If data is int32, those words are random node ids in [0,20000): all-zero over
    // 256 samples is impossible (P ~ 20000^-256).
    int hi = ei[2 * threadIdx.x + 1];
    if (hi != 0) atomicExch(&ok, 0);
    __syncthreads();
    if (threadIdx.x == 0) g_is64 = ok;
}

__global__ void k_zero() {
    int i = blockIdx.x * blockDim.x + threadIdx.x;
    if (i < NSEG) g_cnt_seg[i] = 0u;
    if (i < RR)   g_rel_cnt[i] = 0;
}

__global__ void k_decode(const void* ei, const void* et) {
    int e = blockIdx.x * blockDim.x + threadIdx.x;
    if (e >= NE) return;
    if (g_is64) {
        const long long* a = (const long long*)ei;
        const long long* b = (const long long*)et;
        g_srcA[e] = (int)a[e];
        g_dstA[e] = (int)a[NE + e];
        g_relA[e] = (int)b[e];
    } else {
        const int* a = (const int*)ei;
        const int* b = (const int*)et;
        g_srcA[e] = a[e];
        g_dstA[e] = a[NE + e];
        g_relA[e] = b[e];
    }
}

__global__ void k_count() {
    __shared__ int sh[RR];
    int t = threadIdx.x;
    if (t < RR) sh[t] = 0;
    __syncthreads();
    int e = blockIdx.x * blockDim.x + t;
    if (e < NE) {
        int r = g_relA[e], d = g_dstA[e];
        atomicAdd(&g_cnt_seg[d * RR + r], 1u);
        atomicAdd(&sh[r], 1);
    }
    __syncthreads();
    if (t < RR && sh[t]) atomicAdd(&g_rel_cnt[t], sh[t]);
}

__global__ void k_scan() {
    int acc = 0;
    for (int r = 0; r < RR; r++) {
        g_rel_ptr[r] = acc;
        g_rel_cur[r] = acc;
        acc += g_rel_cnt[r];
    }
    g_rel_ptr[RR] = acc;
}

__global__ void k_scatter() {
    int e = blockIdx.x * blockDim.x + threadIdx.x;
    if (e >= NE) return;
    int r = g_relA[e], s = g_srcA[e], d = g_dstA[e];
    int pos = atomicAdd(&g_rel_cur[r], 1);
    g_epack[pos] = (unsigned)s | ((unsigned)d << 16);
    g_einv[pos]  = 1.0f / (float)g_cnt_seg[d * RR + r];
}

__global__ void k_init(const float* __restrict__ b1, const float* __restrict__ b2,
                       float* __restrict__ out) {
    int i = blockIdx.x * blockDim.x + threadIdx.x;
    if (i >= NN * HID) return;
    int h = i & (HID - 1);
    g_h1[i] = b1[h];
    out[i]  = b2[h];
}

__global__ void k_relu() {
    int i = blockIdx.x * blockDim.x + threadIdx.x;
    if (i < NN * HID) g_h1[i] = fmaxf(g_h1[i], 0.0f);
}

// ---------------- fused gather / tiny-GEMM / scatter-add per relation ----------------
// layer==1: X = Xext (node_emb, F=16),  OUT = g_h1
// layer==2: X = g_h1 (F=128),           OUT = Oext (final output)
// Pseudo-relation RR applies the root weight with src=dst=node, inv=1.
template <int F, int EPB>
__global__ void __launch_bounds__(256)
k_layer(const float* __restrict__ Xext, float* __restrict__ Oext,
        const float* __restrict__ W, const float* __restrict__ Wroot, int layer) {
    extern __shared__ float sm[];
    float* Ws = sm;               // F * HID weights for this relation
    float* hb = sm + F * HID;     // 8 warps * 8 edges * F staging

    const float* X  = (layer == 1) ? Xext : g_h1;
    float*       OUT = (layer == 1) ? g_h1 : Oext;

    const int tid  = threadIdx.x;
    const int lane = tid & 31;
    const int warp = tid >> 5;
    const int lane4 = lane * 4;

    // map block -> (relation, chunk)
    int bid = blockIdx.x, acc = 0, rel = -1, chunk = 0, cnt = 0;
    #pragma unroll 1
    for (int r = 0; r <= RR; r++) {
        int c  = (r < RR) ? g_rel_cnt[r] : NN;
        int nb = (c + EPB - 1) / EPB;
        if (bid < acc + nb) { rel = r; chunk = bid - acc; cnt = c; break; }
        acc += nb;
    }
    if (rel < 0) return;

    const float* Wp = (rel < RR) ? (W + (size_t)rel * F * HID) : Wroot;
    const int base   = (rel < RR) ? g_rel_ptr[rel] : 0;
    const int cstart = chunk * EPB;

    // stage weights into shared memory (coalesced float4)
    for (int i = tid * 4; i < F * HID; i += 256 * 4)
        *(float4*)&Ws[i] = *(const float4*)&Wp[i];
    __syncthreads();

    float* hbw = hb + warp * (8 * F);
    const int ngroups = EPB / 8;

    for (int g = warp; g < ngroups; g += 8) {
        int gbase = cstart + g * 8;
        if (gbase >= cnt) break;

        // per-edge metadata, loaded by lanes 0..7 then broadcast
        int ms = 0, md = 0; float mi = 0.0f;
        if (lane < 8) {
            int gl = gbase + lane;
            if (gl < cnt) {
                if (rel < RR) {
                    unsigned pk = g_epack[base + gl];
                    ms = (int)(pk & 0xFFFFu);
                    md = (int)(pk >> 16);
                    mi = g_einv[base + gl];
                } else {
                    ms = gl; md = gl; mi = 1.0f;   // root pseudo-edge
                }
            }
        }
        int srcs[8], dsts[8]; float invs[8];
        #pragma unroll
        for (int e = 0; e < 8; e++) {
            srcs[e] = __shfl_sync(0xffffffffu, ms, e);
            dsts[e] = __shfl_sync(0xffffffffu, md, e);
            invs[e] = __shfl_sync(0xffffffffu, mi, e);
        }

        __syncwarp();
        // gather 8 source feature rows into shared staging
        if constexpr (F == 16) {
            if (lane < 16) {
                #pragma unroll
                for (int e = 0; e < 8; e++)
                    hbw[e * F + lane] = X[(size_t)srcs[e] * F + lane];
            }
        } else {
            #pragma unroll
            for (int e = 0; e < 8; e++)
                *(float4*)&hbw[e * F + lane4] = *(const float4*)&X[(size_t)srcs[e] * F + lane4];
        }
        __syncwarp();

        // 8-edge x 4-column register tile
        float a0[8], a1[8], a2[8], a3[8];
        #pragma unroll
        for (int e = 0; e < 8; e++) { a0[e] = a1[e] = a2[e] = a3[e] = 0.0f; }

        #pragma unroll 4
        for (int f = 0; f < F; f++) {
            float4 wv = *(float4*)&Ws[f * HID + lane4];
            #pragma unroll
            for (int e = 0; e < 8; e++) {
                float hv = hbw[e * F + f];
                a0[e] += hv * wv.x;
                a1[e] += hv * wv.y;
                a2[e] += hv * wv.z;
                a3[e] += hv * wv.w;
            }
        }

        // scaled vector scatter-add
        #pragma unroll
        for (int e = 0; e < 8; e++) {
            float iv = invs[e];
            if (iv > 0.0f) {
                red_add_v4(OUT + (size_t)dsts[e] * HID + lane4,
                           a0[e] * iv, a1[e] * iv, a2[e] * iv, a3[e] * iv);
            }
        }
        __syncwarp();
    }
}

// ---------------- launch ----------------
extern "C" void kernel_launch(void* const* d_in, const int* in_sizes, int n_in,
                              void* d_out, int out_size) {
    const void*  ei = d_in[0];
    const void*  et = d_in[1];
    const float* x  = (const float*)d_in[2];
    const float* W1 = (const float*)d_in[3];
    const float* r1 = (const float*)d_in[4];
    const float* b1 = (const float*)d_in[5];
    const float* W2 = (const float*)d_in[6];
    const float* r2 = (const float*)d_in[7];
    const float* b2 = (const float*)d_in[8];
    float* out = (float*)d_out;

    const int SM1 = (EMBD * HID + 8 * 8 * EMBD) * 4;   // 12 KB
    const int SM2 = (HID * HID + 8 * 8 * HID) * 4;     // 96 KB

    // One-time attribute opt-in (first, eager, non-captured call). Does not
    // change the work performed per call.
    static bool attr_done = false;
    if (!attr_done) {
        cudaFuncSetAttribute((const void*)k_layer<HID, EPB2>,
                             cudaFuncAttributeMaxDynamicSharedMemorySize, SM2);
        attr_done = true;
    }

    k_sniff  <<<1, 256>>>((const int*)ei);
    k_zero   <<<(NSEG + 255) / 256, 256>>>();
    k_decode <<<(NE + 255) / 256, 256>>>(ei, et);
    k_count  <<<(NE + 255) / 256, 256>>>();
    k_scan   <<<1, 1>>>();
    k_scatter<<<(NE + 255) / 256, 256>>>();
    k_init   <<<(NN * HID + 255) / 256, 256>>>(b1, b2, out);

    // layer 1: EMB=16 -> HID, writes g_h1 (pre-initialized with b1)
    k_layer<EMBD, EPB1><<<GRID1, 256, SM1>>>(x, out, W1, r1, 1);
    k_relu   <<<(NN * HID + 255) / 256, 256>>>();
    // layer 2: HID -> HID, reads g_h1, writes out (pre-initialized with b2)
    k_layer<HID, EPB2><<<GRID2, 256, SM2>>>(x, out, W2, r2, 2);
}